// round 1
// baseline (speedup 1.0000x reference)
#include <cuda_runtime.h>
#include <math.h>

#define MAXN 50000

// scratch (device globals — no allocation allowed)
__device__ float g_chis[MAXN];
__device__ float g_sigA[MAXN];
__device__ float g_epsA[MAXN];
__device__ float g_w[MAXN * 16];
__device__ float g_scal[2];   // pot, vdw

__device__ __forceinline__ float siluf(float z) {
    return z / (1.0f + __expf(-z));
}
__device__ __forceinline__ float sigmf(float z) {
    return 1.0f / (1.0f + __expf(-z));
}

__global__ void k_zero(int N) {
    int i = blockIdx.x * blockDim.x + threadIdx.x;
    if (i < N) { g_chis[i] = 0.f; g_sigA[i] = 0.f; g_epsA[i] = 0.f; }
    if (i < 2) g_scal[i] = 0.f;
}

// ---------------------------------------------------------------------------
// Phase 1: per-edge fused chi/sigma/eps MLPs (64 -> 80 hidden -> 3 scalars),
// scatter-add to nodes.
// ---------------------------------------------------------------------------
__global__ __launch_bounds__(256, 2) void k_phase1(
    const float* __restrict__ x, const int* __restrict__ senders,
    const float* __restrict__ Wc1, const float* __restrict__ Wc2,
    const float* __restrict__ Ws1, const float* __restrict__ Ws2,
    const float* __restrict__ We1, const float* __restrict__ We2,
    int E)
{
    // combined first-layer weights, pre-scaled by 1/sqrt(64),
    // layout [kc(16)][h(80)][4] so inner loop reads one float4 per hidden unit
    __shared__ float sW[64 * 80];
    __shared__ float sw2[80];
    for (int i = threadIdx.x; i < 64 * 80; i += 256) {
        int k = i / 80, h = i - (i / 80) * 80;
        float v;
        if (h < 16)      v = Wc1[k * 16 + h];
        else if (h < 48) v = Ws1[k * 32 + (h - 16)];
        else             v = We1[k * 32 + (h - 48)];
        sW[(k >> 2) * 320 + h * 4 + (k & 3)] = v * 0.125f;
    }
    if (threadIdx.x < 80) {
        int h = threadIdx.x;
        float v;
        if (h < 16)      v = Wc2[h] * 0.25f;                     // 1/sqrt(16)
        else if (h < 48) v = Ws2[h - 16] * 0.17677669529663689f; // 1/sqrt(32)
        else             v = We2[h - 48] * 0.17677669529663689f;
        sw2[h] = v;
    }
    __syncthreads();

    int e = blockIdx.x * 256 + threadIdx.x;
    if (e >= E) return;

    float acc[80];
#pragma unroll
    for (int h = 0; h < 80; h++) acc[h] = 0.f;

    const float4* x4 = reinterpret_cast<const float4*>(x) + (size_t)e * 16;
    const float4* wb = reinterpret_cast<const float4*>(sW);
    for (int kc = 0; kc < 16; kc++) {
        float4 xv = x4[kc];
        const float4* w = wb + kc * 80;
#pragma unroll
        for (int h = 0; h < 80; h++) {
            float4 wv = w[h];
            acc[h] = fmaf(xv.x, wv.x, acc[h]);
            acc[h] = fmaf(xv.y, wv.y, acc[h]);
            acc[h] = fmaf(xv.z, wv.z, acc[h]);
            acc[h] = fmaf(xv.w, wv.w, acc[h]);
        }
    }

    float chi = 0.f, sg = 0.f, ep = 0.f;
#pragma unroll
    for (int h = 0; h < 80; h++) {
        float c = siluf(acc[h]) * sw2[h];
        if (h < 16)      chi += c;
        else if (h < 48) sg += c;
        else             ep += c;
    }
    int s = senders[e];
    atomicAdd(&g_chis[s], chi);
    atomicAdd(&g_sigA[s], sg);
    atomicAdd(&g_epsA[s], ep);
}

// ---------------------------------------------------------------------------
// Phase 2: per-node charges / pot / vdw / w embedding.
// ---------------------------------------------------------------------------
__global__ __launch_bounds__(256) void k_nodes(
    const int* __restrict__ species, const float* __restrict__ radius,
    const float* __restrict__ hardness, const float* __restrict__ charge_embed,
    const float* __restrict__ W_w1, float* __restrict__ out_charges, int N)
{
    __shared__ float sW[17 * 16];
    for (int i = threadIdx.x; i < 272; i += 256)
        sW[i] = W_w1[i] * 0.24253562503633297f;   // 1/sqrt(17)
    __syncthreads();

    int n = blockIdx.x * 256 + threadIdx.x;
    float potc = 0.f, vdwc = 0.f;
    if (n < N) {
        int sp = species[n];
        float gamma = fmaf(4.f, radius[sp], 0.5f);
        float hv = hardness[sp];
        // stable softplus
        float hard = fmaxf(hv, 0.f) + log1pf(__expf(-fabsf(hv)));
        float chis = g_chis[n];
        float q = -chis / hard;
        potc = 0.5f * (hard + 1.f / gamma) * q * q + chis * q;
        float sgv = sigmf(g_sigA[n]) * 0.15f + 0.15f;
        float epv = sigmf(g_epsA[n]) * 1.7f + 0.3f;
        vdwc = sgv * epv;
        out_charges[n] = q;

        const float* ce = charge_embed + (size_t)sp * 16;
        float wv[16];
#pragma unroll
        for (int j = 0; j < 16; j++) wv[j] = q * sW[j];
#pragma unroll
        for (int i = 0; i < 16; i++) {
            float c = ce[i];
#pragma unroll
            for (int j = 0; j < 16; j++)
                wv[j] = fmaf(c, sW[(1 + i) * 16 + j], wv[j]);
        }
        float4* wout = reinterpret_cast<float4*>(g_w) + (size_t)n * 4;
#pragma unroll
        for (int j = 0; j < 4; j++)
            wout[j] = make_float4(wv[4 * j], wv[4 * j + 1], wv[4 * j + 2], wv[4 * j + 3]);
    }
    // warp reduction for pot / vdw
#pragma unroll
    for (int off = 16; off > 0; off >>= 1) {
        potc += __shfl_down_sync(0xffffffffu, potc, off);
        vdwc += __shfl_down_sync(0xffffffffu, vdwc, off);
    }
    if ((threadIdx.x & 31) == 0) {
        atomicAdd(&g_scal[0], potc);
        atomicAdd(&g_scal[1], vdwc);
    }
}

__global__ void k_scal(float* __restrict__ out_pv) {
    if (threadIdx.x == 0) { out_pv[0] = g_scal[0]; out_pv[1] = g_scal[1]; }
}

// ---------------------------------------------------------------------------
// Phase 3: per-edge 80->32->32->32 MLP, envelope, output + V copy.
// ---------------------------------------------------------------------------
__global__ __launch_bounds__(256, 2) void k_phase3(
    const float* __restrict__ x, const float* __restrict__ vectors,
    const float* __restrict__ V, const int* __restrict__ senders,
    const float* __restrict__ Wx1, const float* __restrict__ Wx2,
    const float* __restrict__ Wx3,
    float* __restrict__ out_x, float* __restrict__ out_V, int E)
{
    __shared__ float sW1[80 * 32];
    __shared__ float sW2[32 * 32];
    __shared__ float sW3[32 * 32];
    for (int i = threadIdx.x; i < 80 * 32; i += 256) {
        int k = i >> 5, j = i & 31;
        sW1[(k >> 2) * 128 + j * 4 + (k & 3)] = Wx1[i] * 0.11180339887498949f; // 1/sqrt(80)
    }
    for (int i = threadIdx.x; i < 32 * 32; i += 256) {
        int k = i >> 5, j = i & 31;
        int idx = (k >> 2) * 128 + j * 4 + (k & 3);
        sW2[idx] = Wx2[i] * 0.17677669529663689f;  // 1/sqrt(32)
        sW3[idx] = Wx3[i] * 0.17677669529663689f;
    }
    __syncthreads();

    int e = blockIdx.x * 256 + threadIdx.x;
    if (e >= E) return;

    float acc[32];
#pragma unroll
    for (int j = 0; j < 32; j++) acc[j] = 0.f;

    const float4* x4 = reinterpret_cast<const float4*>(x) + (size_t)e * 16;
    const float4* w1 = reinterpret_cast<const float4*>(sW1);
    for (int kc = 0; kc < 16; kc++) {
        float4 xv = x4[kc];
        const float4* w = w1 + kc * 32;
#pragma unroll
        for (int j = 0; j < 32; j++) {
            float4 wv = w[j];
            acc[j] = fmaf(xv.x, wv.x, acc[j]);
            acc[j] = fmaf(xv.y, wv.y, acc[j]);
            acc[j] = fmaf(xv.z, wv.z, acc[j]);
            acc[j] = fmaf(xv.w, wv.w, acc[j]);
        }
    }
    int s = senders[e];
    const float4* wn = reinterpret_cast<const float4*>(g_w) + (size_t)s * 4;
#pragma unroll
    for (int kc = 0; kc < 4; kc++) {
        float4 xv = wn[kc];
        const float4* w = w1 + (16 + kc) * 32;
#pragma unroll
        for (int j = 0; j < 32; j++) {
            float4 wv = w[j];
            acc[j] = fmaf(xv.x, wv.x, acc[j]);
            acc[j] = fmaf(xv.y, wv.y, acc[j]);
            acc[j] = fmaf(xv.z, wv.z, acc[j]);
            acc[j] = fmaf(xv.w, wv.w, acc[j]);
        }
    }

    float h1[32];
#pragma unroll
    for (int j = 0; j < 32; j++) h1[j] = siluf(acc[j]);

    // layer 2
#pragma unroll
    for (int j = 0; j < 32; j++) acc[j] = 0.f;
    const float4* w2b = reinterpret_cast<const float4*>(sW2);
#pragma unroll
    for (int kc = 0; kc < 8; kc++) {
        float4 xv = make_float4(h1[4 * kc], h1[4 * kc + 1], h1[4 * kc + 2], h1[4 * kc + 3]);
        const float4* w = w2b + kc * 32;
#pragma unroll
        for (int j = 0; j < 32; j++) {
            float4 wv = w[j];
            acc[j] = fmaf(xv.x, wv.x, acc[j]);
            acc[j] = fmaf(xv.y, wv.y, acc[j]);
            acc[j] = fmaf(xv.z, wv.z, acc[j]);
            acc[j] = fmaf(xv.w, wv.w, acc[j]);
        }
    }
#pragma unroll
    for (int j = 0; j < 32; j++) h1[j] = siluf(acc[j]);

    // layer 3 (no activation)
#pragma unroll
    for (int j = 0; j < 32; j++) acc[j] = 0.f;
    const float4* w3b = reinterpret_cast<const float4*>(sW3);
#pragma unroll
    for (int kc = 0; kc < 8; kc++) {
        float4 xv = make_float4(h1[4 * kc], h1[4 * kc + 1], h1[4 * kc + 2], h1[4 * kc + 3]);
        const float4* w = w3b + kc * 32;
#pragma unroll
        for (int j = 0; j < 32; j++) {
            float4 wv = w[j];
            acc[j] = fmaf(xv.x, wv.x, acc[j]);
            acc[j] = fmaf(xv.y, wv.y, acc[j]);
            acc[j] = fmaf(xv.z, wv.z, acc[j]);
            acc[j] = fmaf(xv.w, wv.w, acc[j]);
        }
    }

    // envelope (MAX_RADIUS = 1, p = 6)
    const float* vp = vectors + (size_t)e * 3;
    float vx = vp[0], vy = vp[1], vz = vp[2];
    float u = sqrtf(vx * vx + vy * vy + vz * vz);
    float env = 0.f;
    if (u < 1.f) {
        float u2 = u * u;
        float u3 = u2 * u;
        float u6 = u3 * u3;
        env = 1.f + u6 * (-28.f + u * (48.f - 21.f * u));
    }

    float4* ox = reinterpret_cast<float4*>(out_x) + (size_t)e * 8;
#pragma unroll
    for (int j = 0; j < 8; j++)
        ox[j] = make_float4(env * acc[4 * j], env * acc[4 * j + 1],
                            env * acc[4 * j + 2], env * acc[4 * j + 3]);

    const float4* vin = reinterpret_cast<const float4*>(V) + (size_t)e * 4;
    float4* ov = reinterpret_cast<float4*>(out_V) + (size_t)e * 4;
#pragma unroll
    for (int j = 0; j < 4; j++) ov[j] = vin[j];
}

// ---------------------------------------------------------------------------
// Launch. Input order (metadata): vectors, x, V, senders, species, radius,
// hardness, charge_embed, W_chi1, W_chi2, W_sig1, W_sig2, W_eps1, W_eps2,
// W_w1, W_x1, W_x2, W_x3.
// Output layout: x_out[E*32] | V[E*16] | charges[N] | pot | vdw
// ---------------------------------------------------------------------------
extern "C" void kernel_launch(void* const* d_in, const int* in_sizes, int n_in,
                              void* d_out, int out_size) {
    const float* vectors = (const float*)d_in[0];
    const float* x       = (const float*)d_in[1];
    const float* V       = (const float*)d_in[2];
    const int*   senders = (const int*)d_in[3];
    const int*   species = (const int*)d_in[4];
    const float* radius  = (const float*)d_in[5];
    const float* hardness= (const float*)d_in[6];
    const float* cembed  = (const float*)d_in[7];
    const float* Wc1 = (const float*)d_in[8];
    const float* Wc2 = (const float*)d_in[9];
    const float* Ws1 = (const float*)d_in[10];
    const float* Ws2 = (const float*)d_in[11];
    const float* We1 = (const float*)d_in[12];
    const float* We2 = (const float*)d_in[13];
    const float* Ww1 = (const float*)d_in[14];
    const float* Wx1 = (const float*)d_in[15];
    const float* Wx2 = (const float*)d_in[16];
    const float* Wx3 = (const float*)d_in[17];

    const int E = in_sizes[3];
    const int N = in_sizes[4];

    float* out = (float*)d_out;
    float* out_x       = out;
    float* out_V       = out + (size_t)E * 32;
    float* out_charges = out + (size_t)E * 48;
    float* out_pv      = out + (size_t)E * 48 + N;

    int nb_n = (N + 255) / 256;
    int nb_e = (E + 255) / 256;

    k_zero<<<nb_n, 256>>>(N);
    k_phase1<<<nb_e, 256>>>(x, senders, Wc1, Wc2, Ws1, Ws2, We1, We2, E);
    k_nodes<<<nb_n, 256>>>(species, radius, hardness, cembed, Ww1, out_charges, N);
    k_scal<<<1, 32>>>(out_pv);
    k_phase3<<<nb_e, 256>>>(x, vectors, V, senders, Wx1, Wx2, Wx3, out_x, out_V, E);
}

// round 2
// speedup vs baseline: 1.0527x; 1.0527x over previous
#include <cuda_runtime.h>
#include <math.h>

#define MAXN 50000

// scratch (device globals — no allocation allowed)
__device__ float g_chis[MAXN];
__device__ float g_sigA[MAXN];
__device__ float g_epsA[MAXN];
__device__ float g_w[MAXN * 16];
__device__ float g_scal[2];   // pot, vdw

__device__ __forceinline__ float siluf(float z) {
    return z / (1.0f + __expf(-z));
}
__device__ __forceinline__ float sigmf(float z) {
    return 1.0f / (1.0f + __expf(-z));
}

// ---- packed f32x2 helpers (SASS FFMA2 — only reachable via PTX) ----
__device__ __forceinline__ unsigned long long dup2(float v) {
    unsigned long long r;
    asm("mov.b64 %0, {%1, %1};" : "=l"(r) : "f"(v));
    return r;
}
__device__ __forceinline__ void ffma2(unsigned long long& d,
                                      unsigned long long a,
                                      unsigned long long b) {
    asm("fma.rn.f32x2 %0, %1, %2, %0;" : "+l"(d) : "l"(a), "l"(b));
}
__device__ __forceinline__ float2 unpk(unsigned long long v) {
    float2 f;
    asm("mov.b64 {%0, %1}, %2;" : "=f"(f.x), "=f"(f.y) : "l"(v));
    return f;
}

__global__ void k_zero(int N) {
    int i = blockIdx.x * blockDim.x + threadIdx.x;
    if (i < N) { g_chis[i] = 0.f; g_sigA[i] = 0.f; g_epsA[i] = 0.f; }
    if (i < 2) g_scal[i] = 0.f;
}

// ---------------------------------------------------------------------------
// Phase 1: per-edge fused chi/sigma/eps MLPs (64 -> 80 hidden -> 3 scalars),
// scatter-add to nodes. f32x2-packed over the hidden dimension.
// ---------------------------------------------------------------------------
__global__ __launch_bounds__(256, 2) void k_phase1(
    const float* __restrict__ x, const int* __restrict__ senders,
    const float* __restrict__ Wc1, const float* __restrict__ Wc2,
    const float* __restrict__ Ws1, const float* __restrict__ Ws2,
    const float* __restrict__ We1, const float* __restrict__ We2,
    int E)
{
    // first-layer weights pre-scaled by 1/sqrt(64), layout [k(64)][h(80)]
    __shared__ __align__(16) float sW[64 * 80];
    __shared__ float sw2[80];
    for (int i = threadIdx.x; i < 64 * 80; i += 256) {
        int k = i / 80, h = i - (i / 80) * 80;
        float v;
        if (h < 16)      v = Wc1[k * 16 + h];
        else if (h < 48) v = Ws1[k * 32 + (h - 16)];
        else             v = We1[k * 32 + (h - 48)];
        sW[k * 80 + h] = v * 0.125f;
    }
    if (threadIdx.x < 80) {
        int h = threadIdx.x;
        float v;
        if (h < 16)      v = Wc2[h] * 0.25f;                     // 1/sqrt(16)
        else if (h < 48) v = Ws2[h - 16] * 0.17677669529663689f; // 1/sqrt(32)
        else             v = We2[h - 48] * 0.17677669529663689f;
        sw2[h] = v;
    }
    __syncthreads();

    int e = blockIdx.x * 256 + threadIdx.x;
    if (e >= E) return;

    unsigned long long acc[40];
#pragma unroll
    for (int i = 0; i < 40; i++) acc[i] = 0ull;

    const float4* x4 = reinterpret_cast<const float4*>(x) + (size_t)e * 16;
#pragma unroll 1
    for (int kc = 0; kc < 16; kc++) {
        float4 xv = x4[kc];
#pragma unroll
        for (int sub = 0; sub < 4; sub++) {
            float xs = (sub == 0) ? xv.x : (sub == 1) ? xv.y : (sub == 2) ? xv.z : xv.w;
            unsigned long long xd = dup2(xs);
            const ulonglong2* w =
                reinterpret_cast<const ulonglong2*>(sW + (kc * 4 + sub) * 80);
#pragma unroll
            for (int hp = 0; hp < 20; hp++) {
                ulonglong2 wv = w[hp];
                ffma2(acc[2 * hp],     xd, wv.x);
                ffma2(acc[2 * hp + 1], xd, wv.y);
            }
        }
    }

    float chi = 0.f, sg = 0.f, ep = 0.f;
#pragma unroll
    for (int i = 0; i < 40; i++) {
        float2 f = unpk(acc[i]);
        int h0 = 2 * i;
        float c = siluf(f.x) * sw2[h0] + siluf(f.y) * sw2[h0 + 1];
        if (h0 < 16)      chi += c;
        else if (h0 < 48) sg += c;
        else              ep += c;
    }
    int s = senders[e];
    atomicAdd(&g_chis[s], chi);
    atomicAdd(&g_sigA[s], sg);
    atomicAdd(&g_epsA[s], ep);
}

// ---------------------------------------------------------------------------
// Phase 2: per-node charges / pot / vdw / w embedding.
// ---------------------------------------------------------------------------
__global__ __launch_bounds__(256) void k_nodes(
    const int* __restrict__ species, const float* __restrict__ radius,
    const float* __restrict__ hardness, const float* __restrict__ charge_embed,
    const float* __restrict__ W_w1, float* __restrict__ out_charges, int N)
{
    __shared__ float sW[17 * 16];
    for (int i = threadIdx.x; i < 272; i += 256)
        sW[i] = W_w1[i] * 0.24253562503633297f;   // 1/sqrt(17)
    __syncthreads();

    int n = blockIdx.x * 256 + threadIdx.x;
    float potc = 0.f, vdwc = 0.f;
    if (n < N) {
        int sp = species[n];
        float gamma = fmaf(4.f, radius[sp], 0.5f);
        float hv = hardness[sp];
        float hard = fmaxf(hv, 0.f) + log1pf(__expf(-fabsf(hv)));  // stable softplus
        float chis = g_chis[n];
        float q = -chis / hard;
        potc = 0.5f * (hard + 1.f / gamma) * q * q + chis * q;
        float sgv = sigmf(g_sigA[n]) * 0.15f + 0.15f;
        float epv = sigmf(g_epsA[n]) * 1.7f + 0.3f;
        vdwc = sgv * epv;
        out_charges[n] = q;

        const float* ce = charge_embed + (size_t)sp * 16;
        float wv[16];
#pragma unroll
        for (int j = 0; j < 16; j++) wv[j] = q * sW[j];
#pragma unroll
        for (int i = 0; i < 16; i++) {
            float c = ce[i];
#pragma unroll
            for (int j = 0; j < 16; j++)
                wv[j] = fmaf(c, sW[(1 + i) * 16 + j], wv[j]);
        }
        float4* wout = reinterpret_cast<float4*>(g_w) + (size_t)n * 4;
#pragma unroll
        for (int j = 0; j < 4; j++)
            wout[j] = make_float4(wv[4 * j], wv[4 * j + 1], wv[4 * j + 2], wv[4 * j + 3]);
    }
#pragma unroll
    for (int off = 16; off > 0; off >>= 1) {
        potc += __shfl_down_sync(0xffffffffu, potc, off);
        vdwc += __shfl_down_sync(0xffffffffu, vdwc, off);
    }
    if ((threadIdx.x & 31) == 0) {
        atomicAdd(&g_scal[0], potc);
        atomicAdd(&g_scal[1], vdwc);
    }
}

__global__ void k_scal(float* __restrict__ out_pv) {
    if (threadIdx.x == 0) { out_pv[0] = g_scal[0]; out_pv[1] = g_scal[1]; }
}

// ---------------------------------------------------------------------------
// Phase 3: per-edge 80->32->32->32 MLP, envelope, output + V copy.
// f32x2-packed over the output dimension of every layer.
// ---------------------------------------------------------------------------
__global__ __launch_bounds__(256, 2) void k_phase3(
    const float* __restrict__ x, const float* __restrict__ vectors,
    const float* __restrict__ V, const int* __restrict__ senders,
    const float* __restrict__ Wx1, const float* __restrict__ Wx2,
    const float* __restrict__ Wx3,
    float* __restrict__ out_x, float* __restrict__ out_V, int E)
{
    __shared__ __align__(16) float sW1[80 * 32];
    __shared__ __align__(16) float sW2[32 * 32];
    __shared__ __align__(16) float sW3[32 * 32];
    for (int i = threadIdx.x; i < 80 * 32; i += 256)
        sW1[i] = Wx1[i] * 0.11180339887498949f;  // 1/sqrt(80)
    for (int i = threadIdx.x; i < 32 * 32; i += 256) {
        sW2[i] = Wx2[i] * 0.17677669529663689f;  // 1/sqrt(32)
        sW3[i] = Wx3[i] * 0.17677669529663689f;
    }
    __syncthreads();

    int e = blockIdx.x * 256 + threadIdx.x;
    if (e >= E) return;

    unsigned long long acc[16];
#pragma unroll
    for (int j = 0; j < 16; j++) acc[j] = 0ull;

    // layer 1, rows 0..63: x
    const float4* x4 = reinterpret_cast<const float4*>(x) + (size_t)e * 16;
#pragma unroll 1
    for (int kc = 0; kc < 16; kc++) {
        float4 xv = x4[kc];
#pragma unroll
        for (int sub = 0; sub < 4; sub++) {
            float xs = (sub == 0) ? xv.x : (sub == 1) ? xv.y : (sub == 2) ? xv.z : xv.w;
            unsigned long long xd = dup2(xs);
            const ulonglong2* w =
                reinterpret_cast<const ulonglong2*>(sW1 + (kc * 4 + sub) * 32);
#pragma unroll
            for (int hp = 0; hp < 8; hp++) {
                ulonglong2 wv = w[hp];
                ffma2(acc[2 * hp],     xd, wv.x);
                ffma2(acc[2 * hp + 1], xd, wv.y);
            }
        }
    }
    // layer 1, rows 64..79: w[sender]
    int s = senders[e];
    const float4* wn = reinterpret_cast<const float4*>(g_w) + (size_t)s * 4;
#pragma unroll
    for (int kc = 0; kc < 4; kc++) {
        float4 xv = wn[kc];
#pragma unroll
        for (int sub = 0; sub < 4; sub++) {
            float xs = (sub == 0) ? xv.x : (sub == 1) ? xv.y : (sub == 2) ? xv.z : xv.w;
            unsigned long long xd = dup2(xs);
            const ulonglong2* w =
                reinterpret_cast<const ulonglong2*>(sW1 + (64 + kc * 4 + sub) * 32);
#pragma unroll
            for (int hp = 0; hp < 8; hp++) {
                ulonglong2 wv = w[hp];
                ffma2(acc[2 * hp],     xd, wv.x);
                ffma2(acc[2 * hp + 1], xd, wv.y);
            }
        }
    }

    float h1[32];
#pragma unroll
    for (int j = 0; j < 16; j++) {
        float2 f = unpk(acc[j]);
        h1[2 * j]     = siluf(f.x);
        h1[2 * j + 1] = siluf(f.y);
    }

    // layer 2
#pragma unroll
    for (int j = 0; j < 16; j++) acc[j] = 0ull;
#pragma unroll 2
    for (int k = 0; k < 32; k++) {
        unsigned long long xd = dup2(h1[k]);
        const ulonglong2* w = reinterpret_cast<const ulonglong2*>(sW2 + k * 32);
#pragma unroll
        for (int hp = 0; hp < 8; hp++) {
            ulonglong2 wv = w[hp];
            ffma2(acc[2 * hp],     xd, wv.x);
            ffma2(acc[2 * hp + 1], xd, wv.y);
        }
    }
#pragma unroll
    for (int j = 0; j < 16; j++) {
        float2 f = unpk(acc[j]);
        h1[2 * j]     = siluf(f.x);
        h1[2 * j + 1] = siluf(f.y);
    }

    // layer 3 (no activation)
#pragma unroll
    for (int j = 0; j < 16; j++) acc[j] = 0ull;
#pragma unroll 2
    for (int k = 0; k < 32; k++) {
        unsigned long long xd = dup2(h1[k]);
        const ulonglong2* w = reinterpret_cast<const ulonglong2*>(sW3 + k * 32);
#pragma unroll
        for (int hp = 0; hp < 8; hp++) {
            ulonglong2 wv = w[hp];
            ffma2(acc[2 * hp],     xd, wv.x);
            ffma2(acc[2 * hp + 1], xd, wv.y);
        }
    }

    // envelope (MAX_RADIUS = 1, p = 6)
    const float* vp = vectors + (size_t)e * 3;
    float vx = vp[0], vy = vp[1], vz = vp[2];
    float u = sqrtf(vx * vx + vy * vy + vz * vz);
    float env = 0.f;
    if (u < 1.f) {
        float u2 = u * u;
        float u3 = u2 * u;
        float u6 = u3 * u3;
        env = 1.f + u6 * (-28.f + u * (48.f - 21.f * u));
    }

    float4* ox = reinterpret_cast<float4*>(out_x) + (size_t)e * 8;
#pragma unroll
    for (int j = 0; j < 8; j++) {
        float2 f0 = unpk(acc[2 * j]);
        float2 f1 = unpk(acc[2 * j + 1]);
        ox[j] = make_float4(env * f0.x, env * f0.y, env * f1.x, env * f1.y);
    }

    const float4* vin = reinterpret_cast<const float4*>(V) + (size_t)e * 4;
    float4* ov = reinterpret_cast<float4*>(out_V) + (size_t)e * 4;
#pragma unroll
    for (int j = 0; j < 4; j++) ov[j] = vin[j];
}

// ---------------------------------------------------------------------------
// Launch. Output layout: x_out[E*32] | V[E*16] | charges[N] | pot | vdw
// ---------------------------------------------------------------------------
extern "C" void kernel_launch(void* const* d_in, const int* in_sizes, int n_in,
                              void* d_out, int out_size) {
    const float* vectors = (const float*)d_in[0];
    const float* x       = (const float*)d_in[1];
    const float* V       = (const float*)d_in[2];
    const int*   senders = (const int*)d_in[3];
    const int*   species = (const int*)d_in[4];
    const float* radius  = (const float*)d_in[5];
    const float* hardness= (const float*)d_in[6];
    const float* cembed  = (const float*)d_in[7];
    const float* Wc1 = (const float*)d_in[8];
    const float* Wc2 = (const float*)d_in[9];
    const float* Ws1 = (const float*)d_in[10];
    const float* Ws2 = (const float*)d_in[11];
    const float* We1 = (const float*)d_in[12];
    const float* We2 = (const float*)d_in[13];
    const float* Ww1 = (const float*)d_in[14];
    const float* Wx1 = (const float*)d_in[15];
    const float* Wx2 = (const float*)d_in[16];
    const float* Wx3 = (const float*)d_in[17];

    const int E = in_sizes[3];
    const int N = in_sizes[4];

    float* out = (float*)d_out;
    float* out_x       = out;
    float* out_V       = out + (size_t)E * 32;
    float* out_charges = out + (size_t)E * 48;
    float* out_pv      = out + (size_t)E * 48 + N;

    int nb_n = (N + 255) / 256;
    int nb_e = (E + 255) / 256;

    k_zero<<<nb_n, 256>>>(N);
    k_phase1<<<nb_e, 256>>>(x, senders, Wc1, Wc2, Ws1, Ws2, We1, We2, E);
    k_nodes<<<nb_n, 256>>>(species, radius, hardness, cembed, Ww1, out_charges, N);
    k_scal<<<1, 32>>>(out_pv);
    k_phase3<<<nb_e, 256>>>(x, vectors, V, senders, Wx1, Wx2, Wx3, out_x, out_V, E);
}